// round 4
// baseline (speedup 1.0000x reference)
#include <cuda_runtime.h>

// ---------------------------------------------------------------------------
// ConfidenceAwareSSIM: B=16, C=3, H=W=512, fp32.
// loss = mean( clip(1 - SSIM(x,y), 0, 1) * conf ), 11x11 Gaussian, zero pad.
//
// R4 changes vs R3 (80.4us, fma=58.6% top pipe):
//  * f32x2 packed math (PTX-only on sm_103a; ptxas never emits it from C++).
//    (s,d) and (s^2,d^2) share Gaussian taps -> pack each pair into one
//    64-bit f32x2 register; conv FADD/FFMA chains issue at half the rate.
//  * smem arrays interleaved as float2 -> phase-2 LDS.64, half the LDS instr.
//  * 11-deep ring buffer in vertical pass to stay under the 64-reg cap.
// ---------------------------------------------------------------------------

#define BATCH 16
#define CH    3
#define HH    512
#define WW    512

#define TW    64
#define TH    32
#define HALO  5
#define SH    (TH + 2*HALO)       // 42

#define SMEM_FLOATS (4*SH*TW)     // two float2 arrays: (S,D) and (A,B)
#define SMEM_BYTES  (SMEM_FLOATS * 4)   // 43,008 B

typedef unsigned long long u64;

__device__ __forceinline__ u64 pk2(float a, float b) {
    u64 r; asm("mov.b64 %0,{%1,%2};" : "=l"(r) : "f"(a), "f"(b)); return r;
}
__device__ __forceinline__ float2 up2(u64 v) {
    float2 r; asm("mov.b64 {%0,%1},%2;" : "=f"(r.x), "=f"(r.y) : "l"(v)); return r;
}
__device__ __forceinline__ u64 add2(u64 a, u64 b) {
    u64 r; asm("add.rn.f32x2 %0,%1,%2;" : "=l"(r) : "l"(a), "l"(b)); return r;
}
__device__ __forceinline__ u64 mul2(u64 a, u64 b) {
    u64 r; asm("mul.rn.f32x2 %0,%1,%2;" : "=l"(r) : "l"(a), "l"(b)); return r;
}
__device__ __forceinline__ u64 fma2(u64 a, u64 b, u64 c) {
    u64 r; asm("fma.rn.f32x2 %0,%1,%2,%3;" : "=l"(r) : "l"(a), "l"(b), "l"(c)); return r;
}

// Gaussian taps (symmetric, normalized).
__device__ __forceinline__ constexpr float gw(int k) {
    const int d = (k <= 5) ? k : (10 - k);
    return (d == 0) ? 0.00102838f
         : (d == 1) ? 0.00759876f
         : (d == 2) ? 0.03600078f
         : (d == 3) ? 0.10936070f
         : (d == 4) ? 0.21300554f
         :            0.26601173f;
}

__global__ void zero_out_kernel(float* p) { *p = 0.0f; }

__global__ void __launch_bounds__(256, 4)
ssim_tile_kernel(const float* __restrict__ gx, const float* __restrict__ gy,
                 const float* __restrict__ gconf, float* __restrict__ gout)
{
    extern __shared__ float smem_raw[];
    u64* shSD = reinterpret_cast<u64*>(smem_raw);            // [SH][TW] of (S,D)
    u64* shAB = shSD + SH * TW;                               // [SH][TW] of (A,B)

    const int tid = threadIdx.x;
    const int col = tid & 63;               // phase-2: one column per thread
    const int ry  = tid >> 6;               // phase-2: rows 8*ry .. 8*ry+7
    const int x0  = blockIdx.x * TW;
    const int y0  = blockIdx.y * TH;
    const int b   = blockIdx.z;

    const float C1c = 0.0001f;   // 0.01^2
    const float C2c = 0.0009f;   // 0.03^2

    // packed taps (f32x2 cannot take immediates)
    u64 GW[6];
#pragma unroll
    for (int k = 0; k < 6; ++k) GW[k] = pk2(gw(k), gw(k));

    float lsum[8];
#pragma unroll
    for (int i = 0; i < 8; ++i) lsum[i] = 0.0f;

    for (int c = 0; c < CH; ++c) {
        const float* xb = gx + (size_t)(b * CH + c) * (HH * WW);
        const float* yb = gy + (size_t)(b * CH + c) * (HH * WW);

        // ---- Phase 1: horizontal conv of packed (s,d) and (s^2,d^2) ----
        // Unit (r,g): smem row r, output cols 4g..4g+3. Taps span image cols
        // x0+4g-5 .. x0+4g+8, covered by 5 aligned float4s starting x0+4g-8.
        for (int u = tid; u < SH * 16; u += 256) {
            const int r = u >> 4;
            const int g = u & 15;
            const int grow = y0 + r - HALO;
            const bool rok = (unsigned)grow < (unsigned)HH;
            const float4* xrow = reinterpret_cast<const float4*>(xb + (size_t)grow * WW);
            const float4* yrow = reinterpret_cast<const float4*>(yb + (size_t)grow * WW);
            const int c0 = x0 + 4 * g - 8;     // first float4 col (aligned)

            u64 sd[20];
#pragma unroll
            for (int q = 0; q < 5; ++q) {
                const int gc = c0 + 4 * q;
                float4 fx = make_float4(0.f, 0.f, 0.f, 0.f);
                float4 fy = make_float4(0.f, 0.f, 0.f, 0.f);
                if (rok && (unsigned)gc < (unsigned)WW) {
                    fx = xrow[gc >> 2];
                    fy = yrow[gc >> 2];
                }
                sd[4*q+0] = pk2(fx.x + fy.x, fx.x - fy.x);
                sd[4*q+1] = pk2(fx.y + fy.y, fx.y - fy.y);
                sd[4*q+2] = pk2(fx.z + fy.z, fx.z - fy.z);
                sd[4*q+3] = pk2(fx.w + fy.w, fx.w - fy.w);
            }

            // conv of (s,d): one f32x2 chain does both
#pragma unroll
            for (int j = 0; j < 4; ++j) {
                u64 acc = mul2(GW[5], sd[j+8]);
#pragma unroll
                for (int k = 0; k < 5; ++k)
                    acc = fma2(GW[k], add2(sd[j+3+k], sd[j+13-k]), acc);
                shSD[r * TW + 4 * g + j] = acc;
            }

            // squares (packed) then their conv
            u64 q2[14];
#pragma unroll
            for (int i = 0; i < 14; ++i)
                q2[i] = mul2(sd[i+3], sd[i+3]);
#pragma unroll
            for (int j = 0; j < 4; ++j) {
                u64 acc = mul2(GW[5], q2[j+5]);
#pragma unroll
                for (int k = 0; k < 5; ++k)
                    acc = fma2(GW[k], add2(q2[j+k], q2[j+10-k]), acc);
                shAB[r * TW + 4 * g + j] = acc;
            }
        }
        __syncthreads();

        // ---- Phase 2: vertical conv (8 rows x 1 col), ring buffer ----
        const int rbase = 8 * ry;

        // pass A: (S,D)
        u64 resSD[8];
        {
            const u64* bp = shSD + col;
            u64 v[11];
#pragma unroll
            for (int r = 0; r < 11; ++r)
                v[r] = bp[(rbase + r) * TW];
#pragma unroll
            for (int j = 0; j < 8; ++j) {
                u64 acc = mul2(GW[5], v[(j+5) % 11]);
#pragma unroll
                for (int k = 0; k < 5; ++k)
                    acc = fma2(GW[k], add2(v[(j+k) % 11], v[(j+10-k) % 11]), acc);
                resSD[j] = acc;
                if (j < 7)
                    v[j % 11] = bp[(rbase + 11 + j) * TW];
            }
        }

        // pass B: (A,B), fused SSIM per output row
        {
            const u64* bp = shAB + col;
            u64 v[11];
#pragma unroll
            for (int r = 0; r < 11; ++r)
                v[r] = bp[(rbase + r) * TW];
#pragma unroll
            for (int j = 0; j < 8; ++j) {
                u64 acc = mul2(GW[5], v[(j+5) % 11]);
#pragma unroll
                for (int k = 0; k < 5; ++k)
                    acc = fma2(GW[k], add2(v[(j+k) % 11], v[(j+10-k) % 11]), acc);
                if (j < 7)
                    v[j % 11] = bp[(rbase + 11 + j) * TW];

                const float2 AB = up2(acc);                    // (A, B)
                const float2 PQ = up2(mul2(resSD[j], resSD[j])); // (S^2, D^2)
                const float t1 = 0.5f * (PQ.x - PQ.y);         // 2*mu_x*mu_y
                const float t3 = 0.5f * (PQ.x + PQ.y);         // mu_x^2+mu_y^2
                const float t2 = 0.5f * (AB.x - AB.y) - t1;    // 2*sigma_xy
                const float t4 = 0.5f * (AB.x + AB.y) - t3;    // sx^2+sy^2
                const float num = (t1 + C1c) * (t2 + C2c);
                const float den = (t3 + C1c) * (t4 + C2c);
                float loss = 1.0f - __fdividef(num, den);
                loss = fminf(fmaxf(loss, 0.0f), 1.0f);
                lsum[j] += loss;
            }
        }
        __syncthreads();   // phase-2 reads done before next channel overwrites
    }

    // ---- conf weighting + reduction ----
    float tsum = 0.0f;
    const float* cb = gconf + (size_t)b * (HH * WW)
                    + (size_t)(y0 + 8 * ry) * WW + (x0 + col);
#pragma unroll
    for (int j = 0; j < 8; ++j)
        tsum += lsum[j] * cb[(size_t)j * WW];

#pragma unroll
    for (int off = 16; off > 0; off >>= 1)
        tsum += __shfl_down_sync(0xffffffffu, tsum, off);

    __shared__ float wsum[8];
    if ((tid & 31) == 0) wsum[tid >> 5] = tsum;
    __syncthreads();
    if (tid == 0) {
        float s = 0.0f;
#pragma unroll
        for (int i = 0; i < 8; ++i) s += wsum[i];
        const float inv_n = 1.0f / (float)(BATCH * CH * HH * WW);
        atomicAdd(gout, s * inv_n);
    }
}

extern "C" void kernel_launch(void* const* d_in, const int* in_sizes, int n_in,
                              void* d_out, int out_size)
{
    const float* x    = (const float*)d_in[0];
    const float* y    = (const float*)d_in[1];
    const float* conf = (const float*)d_in[2];
    float* out = (float*)d_out;

    cudaFuncSetAttribute(ssim_tile_kernel,
                         cudaFuncAttributeMaxDynamicSharedMemorySize, SMEM_BYTES);

    zero_out_kernel<<<1, 1>>>(out);

    dim3 grid(WW / TW, HH / TH, BATCH);   // 8 x 16 x 16 = 2048 blocks
    ssim_tile_kernel<<<grid, 256, SMEM_BYTES>>>(x, y, conf, out);
}

// round 5
// speedup vs baseline: 1.0482x; 1.0482x over previous
#include <cuda_runtime.h>

// ---------------------------------------------------------------------------
// ConfidenceAwareSSIM: B=16, C=3, H=W=512, fp32.
// loss = mean( clip(1 - SSIM(x,y), 0, 1) * conf ), 11x11 Gaussian, zero pad.
//
// R5 changes vs R3 (80.4us) / R4 (f32x2 FAILED, pipe-cycles conserved):
//  * back to scalar math (f32x2 reverted).
//  * 64x64 tile (TH=64): vertical-halo overhead in phase 1 drops from
//    42/32=1.31x to 74/64=1.16x  ->  -12% fma/LDG/STS in the dominant phase.
//  * conf folded into phase-2 epilogue (tsum += loss*conf per channel),
//    removing the per-pixel lsum array the taller tile would need.
//  * smem 75.8KB, __launch_bounds__(256,3): 3 CTAs/SM, regs cap 85.
// ---------------------------------------------------------------------------

#define BATCH 16
#define CH    3
#define HH    512
#define WW    512

#define TW    64
#define TH    64
#define HALO  5
#define SH    (TH + 2*HALO)       // 74

#define SMEM_FLOATS (4*SH*TW)     // planes: S, D, A=conv(s^2), B=conv(d^2)
#define SMEM_BYTES  (SMEM_FLOATS * 4)   // 75,776 B

// Gaussian taps (symmetric, normalized) as literals -> FFMA-imm (rt=1).
__device__ __forceinline__ constexpr float gw(int k) {
    const int d = (k <= 5) ? k : (10 - k);
    return (d == 0) ? 0.00102838f
         : (d == 1) ? 0.00759876f
         : (d == 2) ? 0.03600078f
         : (d == 3) ? 0.10936070f
         : (d == 4) ? 0.21300554f
         :            0.26601173f;
}

__global__ void zero_out_kernel(float* p) { *p = 0.0f; }

__global__ void __launch_bounds__(256, 3)
ssim_tile_kernel(const float* __restrict__ gx, const float* __restrict__ gy,
                 const float* __restrict__ gconf, float* __restrict__ gout)
{
    extern __shared__ float sh[];           // [4][SH][TW]

    const int tid = threadIdx.x;
    const int col = tid & 63;               // phase-2: one column per thread
    const int ry  = tid >> 6;               // phase-2: row group
    const int x0  = blockIdx.x * TW;
    const int y0  = blockIdx.y * TH;
    const int b   = blockIdx.z;

    const float C1c = 0.0001f;   // 0.01^2
    const float C2c = 0.0009f;   // 0.03^2

    const float* cbase = gconf + (size_t)b * (HH * WW) + (size_t)y0 * WW + (x0 + col);

    float tsum = 0.0f;           // running sum of loss*conf over all my pixels

    for (int c = 0; c < CH; ++c) {
        const float* xb = gx + (size_t)(b * CH + c) * (HH * WW);
        const float* yb = gy + (size_t)(b * CH + c) * (HH * WW);

        // ---- Phase 1: horizontal conv of {s,d,s^2,d^2} from GLOBAL -> sh ----
        // Unit (r,g): smem row r, output cols 4g..4g+3. Taps span image cols
        // x0+4g-5 .. x0+4g+8, covered by 5 aligned float4s starting x0+4g-8.
        for (int u = tid; u < SH * 16; u += 256) {
            const int r = u >> 4;
            const int g = u & 15;
            const int grow = y0 + r - HALO;
            const bool rok = (unsigned)grow < (unsigned)HH;
            const float4* xrow = reinterpret_cast<const float4*>(xb + (size_t)grow * WW);
            const float4* yrow = reinterpret_cast<const float4*>(yb + (size_t)grow * WW);
            const int c0 = x0 + 4 * g - 8;     // first float4 col (aligned)

            float vs[20], vd[20];
#pragma unroll
            for (int q = 0; q < 5; ++q) {
                const int gc = c0 + 4 * q;
                float4 fx = make_float4(0.f, 0.f, 0.f, 0.f);
                float4 fy = make_float4(0.f, 0.f, 0.f, 0.f);
                if (rok && (unsigned)gc < (unsigned)WW) {
                    fx = xrow[gc >> 2];
                    fy = yrow[gc >> 2];
                }
                vs[4*q+0] = fx.x + fy.x;  vd[4*q+0] = fx.x - fy.x;
                vs[4*q+1] = fx.y + fy.y;  vd[4*q+1] = fx.y - fy.y;
                vs[4*q+2] = fx.z + fy.z;  vd[4*q+2] = fx.z - fy.z;
                vs[4*q+3] = fx.w + fy.w;  vd[4*q+3] = fx.w - fy.w;
            }

            // conv of s and d (store immediately to free accumulators)
#pragma unroll
            for (int j = 0; j < 4; ++j) {
                float hs = gw(5) * vs[j+8];
                float hd = gw(5) * vd[j+8];
#pragma unroll
                for (int k = 0; k < 5; ++k) {
                    hs += gw(k) * (vs[j+3+k] + vs[j+13-k]);
                    hd += gw(k) * (vd[j+3+k] + vd[j+13-k]);
                }
                const int o = r * TW + 4 * g + j;
                sh[0*(SH*TW) + o] = hs;
                sh[1*(SH*TW) + o] = hd;
            }

            // squares (span indices 3..16 -> s2[0..13]) then their conv
            float s2[14], d2[14];
#pragma unroll
            for (int i = 0; i < 14; ++i) {
                s2[i] = vs[i+3] * vs[i+3];
                d2[i] = vd[i+3] * vd[i+3];
            }
#pragma unroll
            for (int j = 0; j < 4; ++j) {
                float hs2 = gw(5) * s2[j+5];
                float hd2 = gw(5) * d2[j+5];
#pragma unroll
                for (int k = 0; k < 5; ++k) {
                    hs2 += gw(k) * (s2[j+k] + s2[j+10-k]);
                    hd2 += gw(k) * (d2[j+k] + d2[j+10-k]);
                }
                const int o = r * TW + 4 * g + j;
                sh[2*(SH*TW) + o] = hs2;
                sh[3*(SH*TW) + o] = hd2;
            }
        }
        __syncthreads();

        // ---- Phase 2: two passes of (8 rows x 1 col), vertical conv + SSIM ----
#pragma unroll
        for (int pass = 0; pass < 2; ++pass) {
            const int rbase = 8 * ry + 32 * pass;

            float resS[8];
            {
                const float* bp = sh + 0*(SH*TW) + col;
                float v[18];
#pragma unroll
                for (int r = 0; r < 18; ++r) v[r] = bp[(rbase + r) * TW];
#pragma unroll
                for (int j = 0; j < 8; ++j) {
                    float a = gw(5) * v[j+5];
#pragma unroll
                    for (int k = 0; k < 5; ++k) a += gw(k) * (v[j+k] + v[j+10-k]);
                    resS[j] = a;
                }
            }

            float t1[8], t3[8];
            {
                const float* bp = sh + 1*(SH*TW) + col;
                float v[18];
#pragma unroll
                for (int r = 0; r < 18; ++r) v[r] = bp[(rbase + r) * TW];
#pragma unroll
                for (int j = 0; j < 8; ++j) {
                    float a = gw(5) * v[j+5];
#pragma unroll
                    for (int k = 0; k < 5; ++k) a += gw(k) * (v[j+k] + v[j+10-k]);
                    const float P = resS[j] * resS[j];
                    const float Q = a * a;
                    t1[j] = 0.5f * (P - Q);        // 2*mu_x*mu_y
                    t3[j] = 0.5f * (P + Q);        // mu_x^2 + mu_y^2
                }
            }

            float resA[8];
            {
                const float* bp = sh + 2*(SH*TW) + col;
                float v[18];
#pragma unroll
                for (int r = 0; r < 18; ++r) v[r] = bp[(rbase + r) * TW];
#pragma unroll
                for (int j = 0; j < 8; ++j) {
                    float a = gw(5) * v[j+5];
#pragma unroll
                    for (int k = 0; k < 5; ++k) a += gw(k) * (v[j+k] + v[j+10-k]);
                    resA[j] = a;
                }
            }

            {
                const float* bp = sh + 3*(SH*TW) + col;
                float v[18];
#pragma unroll
                for (int r = 0; r < 18; ++r) v[r] = bp[(rbase + r) * TW];
#pragma unroll
                for (int j = 0; j < 8; ++j) {
                    float a = gw(5) * v[j+5];
#pragma unroll
                    for (int k = 0; k < 5; ++k) a += gw(k) * (v[j+k] + v[j+10-k]);
                    const float t2 = 0.5f * (resA[j] - a) - t1[j];   // 2*sigma_xy
                    const float t4 = 0.5f * (resA[j] + a) - t3[j];   // sx^2+sy^2
                    const float num = (t1[j] + C1c) * (t2 + C2c);
                    const float den = (t3[j] + C1c) * (t4 + C2c);
                    float loss = 1.0f - __fdividef(num, den);
                    loss = fminf(fmaxf(loss, 0.0f), 1.0f);
                    tsum += loss * cbase[(size_t)(rbase + j) * WW];
                }
            }
        }
        __syncthreads();   // phase-2 reads done before next channel overwrites
    }

    // ---- block reduction + atomic ----
#pragma unroll
    for (int off = 16; off > 0; off >>= 1)
        tsum += __shfl_down_sync(0xffffffffu, tsum, off);

    __shared__ float wsum[8];
    if ((tid & 31) == 0) wsum[tid >> 5] = tsum;
    __syncthreads();
    if (tid == 0) {
        float s = 0.0f;
#pragma unroll
        for (int i = 0; i < 8; ++i) s += wsum[i];
        const float inv_n = 1.0f / (float)(BATCH * CH * HH * WW);
        atomicAdd(gout, s * inv_n);
    }
}

extern "C" void kernel_launch(void* const* d_in, const int* in_sizes, int n_in,
                              void* d_out, int out_size)
{
    const float* x    = (const float*)d_in[0];
    const float* y    = (const float*)d_in[1];
    const float* conf = (const float*)d_in[2];
    float* out = (float*)d_out;

    cudaFuncSetAttribute(ssim_tile_kernel,
                         cudaFuncAttributeMaxDynamicSharedMemorySize, SMEM_BYTES);

    zero_out_kernel<<<1, 1>>>(out);

    dim3 grid(WW / TW, HH / TH, BATCH);   // 8 x 8 x 16 = 1024 blocks
    ssim_tile_kernel<<<grid, 256, SMEM_BYTES>>>(x, y, conf, out);
}